// round 10
// baseline (speedup 1.0000x reference)
#include <cuda_runtime.h>
#include <cstdint>

#define NN    4096
#define NP1   4097
#define NFEAT 512
#define NHID  64
#define NCLS  16
#define NH    8
#define ALPHA 0.2f
#define TILE  128
#define NT    (NN / TILE)   // 32

typedef unsigned long long ull;

// ---- scratch (device globals; no allocation allowed) ----
__device__ __align__(16) float g_h1[NH * NN * NHID];
__device__ float g_ssrc[NH * NN];
__device__ float g_sdst[NH * NN];
__device__ __align__(16) float g_xc[NN * NH * NHID];
__device__ __align__(16) float g_h2[NN * NCLS];
__device__ float g_s2src[NN];
__device__ float g_s2dst[NN];

// sorted scores + permutations + exp caches (written by sort tails)
__device__ float g_ts1[NH * NN];
__device__ int   g_pm1[NH * NN];
__device__ float g_e1a[NH * NN];
__device__ float g_e1b[NH * NN];
__device__ float g_ts2[NN];
__device__ int   g_pm2[NN];
__device__ float g_e2a[NN];
__device__ float g_e2b[NN];

// layer-1 scans, [h][r][c] row-contiguous; within-tile values + cross-tile offsets
__device__ __align__(16) float g_E1[NH * NP1 * NHID];
__device__ __align__(16) float g_F1[NH * NP1 * NHID];
__device__ float g_totA[NH * NT * NHID];
__device__ float g_totB[NH * NT * NHID];
__device__ float g_offE[NH * (NT + 1) * NHID];
__device__ float g_offF[NH * (NT + 1) * NHID];
__device__ float g_es1[NH * NP1];
__device__ float g_fs1[NH * NP1];
__device__ unsigned int g_cnt1[NH];   // last-block counters (reset by sort1)

// layer-2 scans
__device__ float g_E2[NP1 * NCLS];
__device__ float g_F2[NP1 * NCLS];
__device__ float g_es2[NP1];
__device__ float g_fs2[NP1];

__device__ __forceinline__ float elu1(float v) { return v > 0.f ? v : __expf(v) - 1.f; }

// packed f32x2 helpers (sm_103a FFMA2 path)
__device__ __forceinline__ ull pack_dup(float a) {
    ull r;
    asm("mov.b64 %0, {%1, %1};" : "=l"(r) : "r"(__float_as_uint(a)));
    return r;
}
__device__ __forceinline__ void fma2(ull& acc, ull a, ull b) {
    asm("fma.rn.f32x2 %0, %1, %2, %0;" : "+l"(acc) : "l"(a), "l"(b));
}

// ============================================================
// Kernel 1: h1 = x @ Wh (fused per-row score dots in epilogue)
// A tile stored PRE-DUPLICATED as f32x2 pairs (no per-k-step
// pack MOVs in the mainloop: 44 -> 38 issues per 32 FFMA2).
// ============================================================
__global__ __launch_bounds__(256) void gemm1_kernel(const float* __restrict__ x,
                                                    const float* __restrict__ Wh,
                                                    const float* __restrict__ ah) {
    __shared__ __align__(16) ull   sxT2[16][130];   // [k][row] duplicated pairs
    __shared__ __align__(16) float sW[16][132];     // [k][col]
    const int r0 = blockIdx.x * 128;
    const int by = blockIdx.y;
    const int tid = threadIdx.x;
    const int tx = tid & 15, ty = tid >> 4;

    ull acc[8][4] = {};

    float4 px0, px1, pw0, pw1;
    {
        int e0 = tid, e1 = tid + 256;
        int r_ = e0 >> 2, kq = e0 & 3;
        px0 = *(const float4*)&x[(r0 + r_) * NFEAT + kq * 4];
        r_ = e1 >> 2; kq = e1 & 3;
        px1 = *(const float4*)&x[(r0 + r_) * NFEAT + kq * 4];
        int k_ = e0 >> 5, cq = e0 & 31;
        pw0 = *(const float4*)&Wh[((2 * by + (cq >> 4)) * NFEAT + k_) * NHID + (cq & 15) * 4];
        k_ = e1 >> 5; cq = e1 & 31;
        pw1 = *(const float4*)&Wh[((2 * by + (cq >> 4)) * NFEAT + k_) * NHID + (cq & 15) * 4];
    }

    for (int kt = 0; kt < NFEAT / 16; kt++) {
        __syncthreads();
        {
            int e0 = tid, e1 = tid + 256;
            int r_ = e0 >> 2, kq = e0 & 3;
            sxT2[kq * 4 + 0][r_] = pack_dup(px0.x); sxT2[kq * 4 + 1][r_] = pack_dup(px0.y);
            sxT2[kq * 4 + 2][r_] = pack_dup(px0.z); sxT2[kq * 4 + 3][r_] = pack_dup(px0.w);
            r_ = e1 >> 2; kq = e1 & 3;
            sxT2[kq * 4 + 0][r_] = pack_dup(px1.x); sxT2[kq * 4 + 1][r_] = pack_dup(px1.y);
            sxT2[kq * 4 + 2][r_] = pack_dup(px1.z); sxT2[kq * 4 + 3][r_] = pack_dup(px1.w);
            int k_ = e0 >> 5, cq = e0 & 31;
            *(float4*)&sW[k_][cq * 4] = pw0;
            k_ = e1 >> 5; cq = e1 & 31;
            *(float4*)&sW[k_][cq * 4] = pw1;
        }
        __syncthreads();
        if (kt + 1 < NFEAT / 16) {
            int k0 = (kt + 1) * 16;
            int e0 = tid, e1 = tid + 256;
            int r_ = e0 >> 2, kq = e0 & 3;
            px0 = *(const float4*)&x[(r0 + r_) * NFEAT + k0 + kq * 4];
            r_ = e1 >> 2; kq = e1 & 3;
            px1 = *(const float4*)&x[(r0 + r_) * NFEAT + k0 + kq * 4];
            int k_ = e0 >> 5, cq = e0 & 31;
            pw0 = *(const float4*)&Wh[((2 * by + (cq >> 4)) * NFEAT + k0 + k_) * NHID + (cq & 15) * 4];
            k_ = e1 >> 5; cq = e1 & 31;
            pw1 = *(const float4*)&Wh[((2 * by + (cq >> 4)) * NFEAT + k0 + k_) * NHID + (cq & 15) * 4];
        }
        #pragma unroll
        for (int k = 0; k < 16; k++) {
            ulonglong2 aP0 = *(const ulonglong2*)&sxT2[k][ty * 8];
            ulonglong2 aP1 = *(const ulonglong2*)&sxT2[k][ty * 8 + 2];
            ulonglong2 aP2 = *(const ulonglong2*)&sxT2[k][ty * 8 + 4];
            ulonglong2 aP3 = *(const ulonglong2*)&sxT2[k][ty * 8 + 6];
            ulonglong2 bA = *(const ulonglong2*)&sW[k][tx * 8];
            ulonglong2 bB = *(const ulonglong2*)&sW[k][tx * 8 + 4];
            ull pa[8] = { aP0.x, aP0.y, aP1.x, aP1.y, aP2.x, aP2.y, aP3.x, aP3.y };
            #pragma unroll
            for (int i = 0; i < 8; i++) {
                fma2(acc[i][0], pa[i], bA.x);
                fma2(acc[i][1], pa[i], bA.y);
                fma2(acc[i][2], pa[i], bB.x);
                fma2(acc[i][3], pa[i], bB.y);
            }
        }
    }

    const int head = 2 * by + (tx >> 3);
    const int cb = (tx * 8) & 63;
    float4 as0 = *(const float4*)&ah[head * 2 * NHID + cb];
    float4 as1 = *(const float4*)&ah[head * 2 * NHID + cb + 4];
    float4 ad0 = *(const float4*)&ah[head * 2 * NHID + NHID + cb];
    float4 ad1 = *(const float4*)&ah[head * 2 * NHID + NHID + cb + 4];
    #pragma unroll
    for (int i = 0; i < 8; i++) {
        int r = r0 + ty * 8 + i;
        float4 lo, hi;
        lo.x = __uint_as_float((unsigned)acc[i][0]);  lo.y = __uint_as_float((unsigned)(acc[i][0] >> 32));
        lo.z = __uint_as_float((unsigned)acc[i][1]);  lo.w = __uint_as_float((unsigned)(acc[i][1] >> 32));
        hi.x = __uint_as_float((unsigned)acc[i][2]);  hi.y = __uint_as_float((unsigned)(acc[i][2] >> 32));
        hi.z = __uint_as_float((unsigned)acc[i][3]);  hi.w = __uint_as_float((unsigned)(acc[i][3] >> 32));
        *(float4*)&g_h1[(head * NN + r) * NHID + cb]     = lo;
        *(float4*)&g_h1[(head * NN + r) * NHID + cb + 4] = hi;
        float ss = lo.x*as0.x + lo.y*as0.y + lo.z*as0.z + lo.w*as0.w
                 + hi.x*as1.x + hi.y*as1.y + hi.z*as1.z + hi.w*as1.w;
        float sd = lo.x*ad0.x + lo.y*ad0.y + lo.z*ad0.z + lo.w*ad0.w
                 + hi.x*ad1.x + hi.y*ad1.y + hi.z*ad1.z + hi.w*ad1.w;
        #pragma unroll
        for (int o = 4; o; o >>= 1) {
            ss += __shfl_xor_sync(0xffffffffu, ss, o);
            sd += __shfl_xor_sync(0xffffffffu, sd, o);
        }
        if ((tx & 7) == 0) {
            g_ssrc[head * NN + r] = ss;
            g_sdst[head * NN + r] = sd;
        }
    }
}

// ============================================================
// Bitonic sort (warp-local shfl for j<=16) + fused exp caches
// + fused scalar prefix/suffix scans (es/fs) in the tail.
// ============================================================
__device__ void sortex_body(float* sv, int* si_, float* wtA, float* wtB,
                            const float* __restrict__ src,
                            float* ts, int* pm, float* ea_o, float* eb_o,
                            float* es_, float* fs_) {
    const int tid = threadIdx.x, lane = tid & 31, w = tid >> 5;
    for (int i = tid; i < 4096; i += 1024) { sv[i] = src[i]; si_[i] = i; }
    __syncthreads();

    #pragma unroll
    for (int gg = 0; gg < 4; gg++) {
        int g = w * 4 + gg, i = g * 32 + lane;
        float v = sv[i]; int id = si_[i];
        #pragma unroll
        for (int k = 2; k <= 32; k <<= 1) {
            bool up = ((i & k) == 0);
            #pragma unroll
            for (int j = k >> 1; j; j >>= 1) {
                float ov = __shfl_xor_sync(0xffffffffu, v, j);
                int   oi = __shfl_xor_sync(0xffffffffu, id, j);
                bool lower = (lane & j) == 0;
                bool agtb = lower ? (v > ov) : (ov > v);
                if (agtb == up) { v = ov; id = oi; }
            }
        }
        sv[i] = v; si_[i] = id;
    }
    __syncthreads();

    for (int k = 64; k <= 4096; k <<= 1) {
        for (int j = k >> 1; j >= 32; j >>= 1) {
            #pragma unroll
            for (int q = 0; q < 4; q++) {
                int i = tid + q * 1024;
                int ixj = i ^ j;
                if (ixj > i) {
                    bool up = ((i & k) == 0);
                    float a = sv[i], b = sv[ixj];
                    if ((a > b) == up) {
                        sv[i] = b; sv[ixj] = a;
                        int t = si_[i]; si_[i] = si_[ixj]; si_[ixj] = t;
                    }
                }
            }
            __syncthreads();
        }
        #pragma unroll
        for (int gg = 0; gg < 4; gg++) {
            int g = w * 4 + gg, i = g * 32 + lane;
            float v = sv[i]; int id = si_[i];
            bool up = ((i & k) == 0);
            #pragma unroll
            for (int j = 16; j; j >>= 1) {
                float ov = __shfl_xor_sync(0xffffffffu, v, j);
                int   oi = __shfl_xor_sync(0xffffffffu, id, j);
                bool lower = (lane & j) == 0;
                bool agtb = lower ? (v > ov) : (ov > v);
                if (agtb == up) { v = ov; id = oi; }
            }
            sv[i] = v; si_[i] = id;
        }
        __syncthreads();
    }

    // tail: write sorted arrays + exp caches + scalar scans
    const int base = tid * 4;
    float eaz[4], ebz[4];
    #pragma unroll
    for (int q = 0; q < 4; q++) {
        float t = sv[base + q];
        eaz[q] = __expf(t); ebz[q] = __expf(ALPHA * t);
        ts[base + q] = t; pm[base + q] = si_[base + q];
        ea_o[base + q] = eaz[q]; eb_o[base + q] = ebz[q];
    }
    float sumB = ebz[0] + ebz[1] + ebz[2] + ebz[3];
    float sumA = eaz[0] + eaz[1] + eaz[2] + eaz[3];
    float inclB = sumB;
    #pragma unroll
    for (int o = 1; o < 32; o <<= 1) { float t = __shfl_up_sync(0xffffffffu, inclB, o); if (lane >= o) inclB += t; }
    float sufA = sumA;
    #pragma unroll
    for (int o = 1; o < 32; o <<= 1) { float t = __shfl_down_sync(0xffffffffu, sufA, o); if (lane + o < 32) sufA += t; }
    if (lane == 31) wtB[w] = inclB;
    if (lane == 0)  wtA[w] = sufA;
    __syncthreads();
    float prevB = 0.f, aftA = 0.f;
    for (int ww = 0; ww < 32; ww++) { if (ww < w) prevB += wtB[ww]; if (ww > w) aftA += wtA[ww]; }
    float exB = prevB + inclB - sumB;
    float sfA = aftA + sufA;
    #pragma unroll
    for (int q = 0; q < 4; q++) {
        fs_[base + q] = exB;
        es_[base + q] = sfA;
        exB += ebz[q];
        sfA -= eaz[q];
    }
    if (tid == 1023) { fs_[4096] = exB; es_[4096] = 0.f; }
}

__global__ __launch_bounds__(1024) void sort1_kernel() {
    __shared__ float sv[4096]; __shared__ int si_[4096];
    __shared__ float wtA[32], wtB[32];
    const int h = blockIdx.x;
    if (threadIdx.x == 0) g_cnt1[h] = 0;   // reset last-block counter (graph-replay safe)
    sortex_body(sv, si_, wtA, wtB, g_sdst + h * NN, g_ts1 + h * NN, g_pm1 + h * NN,
                g_e1a + h * NN, g_e1b + h * NN, g_es1 + h * NP1, g_fs1 + h * NP1);
}
__global__ __launch_bounds__(1024) void sort2_kernel() {
    __shared__ float sv[4096]; __shared__ int si_[4096];
    __shared__ float wtA[32], wtB[32];
    sortex_body(sv, si_, wtA, wtB, g_s2dst, g_ts2, g_pm2, g_e2a, g_e2b, g_es2, g_fs2);
}

// ============================================================
// scan1: rank-tile blocks, 2-pass gather (E via tile-total minus
// running prefix), coalesced [r][c] E/F. FUSED cross-tile offsets:
// last finishing block per head computes offE/offF (kills off1).
// ============================================================
__global__ void scan1_kernel() {
    const int h  = blockIdx.y;
    const int tt = blockIdx.x;
    const int tid = threadIdx.x;
    const int c = tid & 63, sub = tid >> 6;
    const int kb = tt * TILE + sub * 32;
    const int hb = h * NN;
    __shared__ float sA[4][64], sB[4][64];
    __shared__ unsigned int isLast;

    // pass 1: sub totals
    float aT = 0.f, bT = 0.f;
    #pragma unroll 4
    for (int m = 0; m < 32; m++) {
        int idx = kb + m;
        float hv = g_h1[(hb + g_pm1[hb + idx]) * NHID + c];
        aT += g_e1a[hb + idx] * hv;
        bT += g_e1b[hb + idx] * hv;
    }
    sA[sub][c] = aT; sB[sub][c] = bT;
    __syncthreads();
    float offb = 0.f, offa = 0.f;
    #pragma unroll
    for (int s = 0; s < 4; s++) { if (s < sub) offb += sB[s][c]; if (s > sub) offa += sA[s][c]; }

    // pass 2: write F (prefix) and E (suffix = total - prefix) in one gather
    float fb = offb, pa = 0.f;
    #pragma unroll 4
    for (int m = 0; m < 32; m++) {
        int idx = kb + m;
        float hv = g_h1[(hb + g_pm1[hb + idx]) * NHID + c];
        float prA = g_e1a[hb + idx] * hv;
        float prB = g_e1b[hb + idx] * hv;
        g_F1[(h * NP1 + idx) * NHID + c] = fb;
        g_E1[(h * NP1 + idx) * NHID + c] = offa + (aT - pa);
        fb += prB;
        pa += prA;
    }
    if (sub == 0) {
        g_totA[(h * NT + tt) * NHID + c] = sA[0][c] + sA[1][c] + sA[2][c] + sA[3][c];
        g_totB[(h * NT + tt) * NHID + c] = sB[0][c] + sB[1][c] + sB[2][c] + sB[3][c];
    }
    __threadfence();
    __syncthreads();
    if (tid == 0) isLast = (atomicAdd(&g_cnt1[h], 1u) == NT - 1);
    __syncthreads();
    if (isLast) {
        // this block is the last for head h: all totals visible. Compute
        // cross-tile offsets: warp w handles cols 8w..8w+7, lane = tile.
        const int w = tid >> 5, lane = tid & 31;
        #pragma unroll
        for (int cc = 0; cc < 8; cc++) {
            const int col = w * 8 + cc;
            const float a = g_totA[(h * NT + lane) * NHID + col];
            const float b = g_totB[(h * NT + lane) * NHID + col];
            float ib = b;
            #pragma unroll
            for (int o = 1; o < 32; o <<= 1) {
                float t = __shfl_up_sync(0xffffffffu, ib, o);
                if (lane >= o) ib += t;
            }
            float sa = a;
            #pragma unroll
            for (int o = 1; o < 32; o <<= 1) {
                float t = __shfl_down_sync(0xffffffffu, sa, o);
                if (lane + o < 32) sa += t;
            }
            g_offF[(h * (NT + 1) + lane) * NHID + col] = ib - b;
            g_offE[(h * (NT + 1) + lane) * NHID + col] = sa - a;
            if (lane == 31) {
                g_offF[(h * (NT + 1) + NT) * NHID + col] = ib;
                g_offE[(h * (NT + 1) + NT) * NHID + col] = 0.f;
            }
            if (lane == 0) {
                g_E1[(h * NP1 + NN) * NHID + col] = 0.f;
                g_F1[(h * NP1 + NN) * NHID + col] = 0.f;
            }
        }
    }
}

// ============================================================
// row1: parallel-lane binary searches, batched gathers -> xc.
// ============================================================
__global__ void row1_kernel() {
    __shared__ float st[4096];
    const int h = blockIdx.y;
    const int warp = threadIdx.x >> 5, lane = threadIdx.x & 31;
    for (int q = threadIdx.x; q < 4096; q += 256) st[q] = g_ts1[h * NN + q];
    __syncthreads();
    const int rbase = blockIdx.x * 64 + warp * 8;
    const float s_l = g_ssrc[h * NN + rbase + (lane & 7)];
    const float w1_l = __expf(s_l), w2_l = __expf(ALPHA * s_l);
    int lo = 0, hi = 4096; const float thr = -s_l;
    while (lo < hi) { int mid = (lo + hi) >> 1; if (st[mid] <= thr) lo = mid + 1; else hi = mid; }

    #pragma unroll
    for (int half = 0; half < 2; half++) {
        int rA[4]; float w1A[4], w2A[4];
        #pragma unroll
        for (int q = 0; q < 4; q++) {
            int rr = half * 4 + q;
            rA[q]  = __shfl_sync(0xffffffffu, lo, rr);
            w1A[q] = __shfl_sync(0xffffffffu, w1_l, rr);
            w2A[q] = __shfl_sync(0xffffffffu, w2_l, rr);
        }
        float e0[4], e1v[4], f0[4], f1v[4], oe0[4], oe1[4], of0[4], of1[4], dn1[4], dn2[4];
        #pragma unroll
        for (int q = 0; q < 4; q++) {
            int r = rA[q], tt = r >> 7;
            const float* E  = &g_E1[(h * NP1 + r) * NHID];
            const float* F  = &g_F1[(h * NP1 + r) * NHID];
            const float* OE = &g_offE[(h * (NT + 1) + tt) * NHID];
            const float* OF = &g_offF[(h * (NT + 1) + tt) * NHID];
            e0[q] = E[lane];  e1v[q] = E[lane + 32];
            f0[q] = F[lane];  f1v[q] = F[lane + 32];
            oe0[q] = OE[lane]; oe1[q] = OE[lane + 32];
            of0[q] = OF[lane]; of1[q] = OF[lane + 32];
            dn1[q] = g_es1[h * NP1 + r]; dn2[q] = g_fs1[h * NP1 + r];
        }
        #pragma unroll
        for (int q = 0; q < 4; q++) {
            int i = rbase + half * 4 + q;
            float inv = 1.f / (w1A[q] * dn1[q] + w2A[q] * dn2[q]);
            float va = (w1A[q] * (e0[q]  + oe0[q]) + w2A[q] * (f0[q]  + of0[q])) * inv;
            float vb = (w1A[q] * (e1v[q] + oe1[q]) + w2A[q] * (f1v[q] + of1[q])) * inv;
            g_xc[i * (NH * NHID) + h * NHID + lane]      = elu1(va);
            g_xc[i * (NH * NHID) + h * NHID + lane + 32] = elu1(vb);
        }
    }
}

// ============================================================
// gemm2: h2 = xc @ Wo + layer-2 score dots
// ============================================================
__global__ void gemm2_kernel(const float* __restrict__ Wo, const float* __restrict__ ao) {
    __shared__ __align__(16) float sxcT[32][68];
    __shared__ __align__(16) float sWo[32][20];
    __shared__ __align__(16) float sh2s[64][17];
    const int r0 = blockIdx.x * 64;
    const int tid = threadIdx.x;
    const int c4 = tid & 3, r = tid >> 2;
    float acc[4] = {};

    for (int k0 = 0; k0 < NFEAT; k0 += 32) {
        __syncthreads();
        #pragma unroll
        for (int i = tid; i < 2048; i += 256) {
            int k = i & 31, rr = i >> 5;
            sxcT[k][rr] = g_xc[(r0 + rr) * NFEAT + k0 + k];
        }
        #pragma unroll
        for (int i = tid; i < 512; i += 256) {
            int k = i >> 4, c = i & 15;
            sWo[k][c] = Wo[(k0 + k) * NCLS + c];
        }
        __syncthreads();
        #pragma unroll
        for (int k = 0; k < 32; k++) {
            float a = sxcT[k][r];
            float4 b = *(const float4*)&sWo[k][c4 * 4];
            acc[0] += a * b.x; acc[1] += a * b.y; acc[2] += a * b.z; acc[3] += a * b.w;
        }
    }
    *(float4*)&g_h2[(r0 + r) * NCLS + c4 * 4] = make_float4(acc[0], acc[1], acc[2], acc[3]);
    sh2s[r][c4 * 4 + 0] = acc[0];
    sh2s[r][c4 * 4 + 1] = acc[1];
    sh2s[r][c4 * 4 + 2] = acc[2];
    sh2s[r][c4 * 4 + 3] = acc[3];
    __syncthreads();
    if (tid < 64) {
        float ss = 0.f, sd = 0.f;
        #pragma unroll
        for (int c = 0; c < NCLS; c++) {
            float hv = sh2s[tid][c];
            ss += hv * ao[c];
            sd += hv * ao[NCLS + c];
        }
        g_s2src[r0 + tid] = ss;
        g_s2dst[r0 + tid] = sd;
    }
}

// ============================================================
// scan2: per-column scans for layer 2
// ============================================================
__device__ __forceinline__ void chunk_offsets(const float* totA, const float* totB,
                                              float* offA, float* offB, int tid) {
    if (tid < 32) {
        float pb[8], pa[8];
        float sb = 0.f, sa = 0.f;
        #pragma unroll
        for (int j = 0; j < 8; j++) { sb += totB[tid * 8 + j]; pb[j] = sb; }
        #pragma unroll
        for (int j = 7; j >= 0; j--) { sa += totA[tid * 8 + j]; pa[j] = sa; }
        float eb = sb;
        #pragma unroll
        for (int o = 1; o < 32; o <<= 1) {
            float t = __shfl_up_sync(0xffffffffu, eb, o);
            if (tid >= o) eb += t;
        }
        eb -= sb;
        float ea = sa;
        #pragma unroll
        for (int o = 1; o < 32; o <<= 1) {
            float t = __shfl_down_sync(0xffffffffu, ea, o);
            if (tid + o < 32) ea += t;
        }
        ea -= sa;
        #pragma unroll
        for (int j = 0; j < 8; j++) {
            offB[tid * 8 + j + 1] = eb + pb[j];
            offA[tid * 8 + j]     = ea + pa[j];
        }
        if (tid == 0)  offB[0]   = 0.f;
        if (tid == 31) offA[256] = 0.f;
    }
}

__global__ void scan2_kernel() {
    const int c = blockIdx.x;
    const int tid = threadIdx.x;
    __shared__ float totA[256], totB[256];
    __shared__ float offA[257], offB[257];
    float a_loc[16], b_loc[16];
    const int base = tid * 16;
    #pragma unroll
    for (int q = 0; q < 16; q++) {
        int k = base + q;
        float hv = g_h2[g_pm2[k] * NCLS + c];
        a_loc[q] = g_e2a[k] * hv;
        b_loc[q] = g_e2b[k] * hv;
    }
    #pragma unroll
    for (int q = 1; q < 16; q++) b_loc[q] += b_loc[q - 1];
    #pragma unroll
    for (int q = 14; q >= 0; q--) a_loc[q] += a_loc[q + 1];
    totB[tid] = b_loc[15]; totA[tid] = a_loc[0];
    __syncthreads();
    chunk_offsets(totA, totB, offA, offB, tid);
    __syncthreads();
    const float ob = offB[tid];
    const float oa = offA[tid + 1];
    float* E = g_E2 + c;
    float* F = g_F2 + c;
    #pragma unroll
    for (int q = 0; q < 16; q++) {
        E[(base + q) * NCLS]     = a_loc[q] + oa;
        F[(base + q + 1) * NCLS] = b_loc[q] + ob;
    }
    if (tid == 0)   F[0] = 0.f;
    if (tid == 255) E[NN * NCLS] = 0.f;
}

// ============================================================
// row2: parallel-lane searches + combine + elu + log_softmax
// ============================================================
__global__ void row2_kernel(float* __restrict__ out) {
    __shared__ float st[4096];
    const int warp = threadIdx.x >> 5, lane = threadIdx.x & 31;
    for (int q = threadIdx.x; q < 4096; q += 256) st[q] = g_ts2[q];
    __syncthreads();
    const int rbase = blockIdx.x * 64 + warp * 8;
    const float s_l = g_s2src[rbase + (lane & 7)];
    const float w1_l = __expf(s_l), w2_l = __expf(ALPHA * s_l);
    int lo = 0, hi = 4096; const float thr = -s_l;
    while (lo < hi) { int mid = (lo + hi) >> 1; if (st[mid] <= thr) lo = mid + 1; else hi = mid; }

    #pragma unroll
    for (int rr = 0; rr < 8; rr++) {
        const int i = rbase + rr;
        const int r  = __shfl_sync(0xffffffffu, lo, rr);
        const float w1 = __shfl_sync(0xffffffffu, w1_l, rr);
        const float w2 = __shfl_sync(0xffffffffu, w2_l, rr);
        const float den = w1 * g_es2[r] + w2 * g_fs2[r];
        const float invden = 1.f / den;
        float v = -1e30f;
        if (lane < NCLS)
            v = elu1((w1 * g_E2[r * NCLS + lane] + w2 * g_F2[r * NCLS + lane]) * invden);
        float m = v;
        #pragma unroll
        for (int o = 8; o; o >>= 1) m = fmaxf(m, __shfl_xor_sync(0xffffffffu, m, o));
        float s = __expf(v - m);
        #pragma unroll
        for (int o = 8; o; o >>= 1) s += __shfl_xor_sync(0xffffffffu, s, o);
        const float lse = m + __logf(s);
        if (lane < NCLS) out[i * NCLS + lane] = v - lse;
    }
}

// ============================================================
extern "C" void kernel_launch(void* const* d_in, const int* in_sizes, int n_in,
                              void* d_out, int out_size) {
    const float* x  = (const float*)d_in[0];
    const float* Wh = (const float*)d_in[1];
    const float* ah = (const float*)d_in[2];
    const float* Wo = (const float*)d_in[3];
    const float* ao = (const float*)d_in[4];
    float* out = (float*)d_out;

    gemm1_kernel<<<dim3(NN / 128, 4), 256>>>(x, Wh, ah);
    sort1_kernel<<<NH, 1024>>>();
    scan1_kernel<<<dim3(NT, NH), 256>>>();
    row1_kernel<<<dim3(NN / 64, NH), 256>>>();
    gemm2_kernel<<<NN / 64, 256>>>(Wo, ao);
    sort2_kernel<<<1, 1024>>>();
    scan2_kernel<<<NCLS, 256>>>();
    row2_kernel<<<NN / 64, 256>>>(out);
}

// round 12
// speedup vs baseline: 1.0491x; 1.0491x over previous
#include <cuda_runtime.h>
#include <cstdint>

#define NN    4096
#define NP1   4097
#define NFEAT 512
#define NHID  64
#define NCLS  16
#define NH    8
#define ALPHA 0.2f
#define TILE  128
#define NT    (NN / TILE)   // 32

typedef unsigned long long ull;

// ---- scratch (device globals; no allocation allowed) ----
__device__ __align__(16) float g_h1[NH * NN * NHID];
__device__ float g_ssrc[NH * NN];
__device__ float g_sdst[NH * NN];
__device__ __align__(16) float g_xc[NN * NH * NHID];
__device__ __align__(16) float g_h2[NN * NCLS];
__device__ float g_s2src[NN];
__device__ float g_s2dst[NN];

// sorted scores + permutations + exp caches (written by sort tails)
__device__ float g_ts1[NH * NN];
__device__ int   g_pm1[NH * NN];
__device__ float g_e1a[NH * NN];
__device__ float g_e1b[NH * NN];
__device__ float g_ts2[NN];
__device__ int   g_pm2[NN];
__device__ float g_e2a[NN];
__device__ float g_e2b[NN];

// layer-1 scans, [h][r][c] row-contiguous; within-tile values + cross-tile offsets
__device__ __align__(16) float g_E1[NH * NP1 * NHID];
__device__ __align__(16) float g_F1[NH * NP1 * NHID];
__device__ float g_totA[NH * NT * NHID];
__device__ float g_totB[NH * NT * NHID];
__device__ float g_offE[NH * (NT + 1) * NHID];
__device__ float g_offF[NH * (NT + 1) * NHID];
__device__ float g_es1[NH * NP1];
__device__ float g_fs1[NH * NP1];
__device__ unsigned int g_cnt1[NH];   // last-block counters (reset by sort1)

// layer-2 scans
__device__ float g_E2[NP1 * NCLS];
__device__ float g_F2[NP1 * NCLS];
__device__ float g_es2[NP1];
__device__ float g_fs2[NP1];

__device__ __forceinline__ float elu1(float v) { return v > 0.f ? v : __expf(v) - 1.f; }

// packed f32x2 helpers (sm_103a FFMA2 path)
// pack_dup is an ALU-pipe MOV that dual-issues alongside fma-pipe FFMA2 —
// keeping it in the mainloop is CHEAPER than pre-duplicating in smem
// (which costs +50% LDS/MIO traffic; measured regression in round 10).
__device__ __forceinline__ ull pack_dup(float a) {
    ull r;
    asm("mov.b64 %0, {%1, %1};" : "=l"(r) : "r"(__float_as_uint(a)));
    return r;
}
__device__ __forceinline__ void fma2(ull& acc, ull a, ull b) {
    asm("fma.rn.f32x2 %0, %1, %2, %0;" : "+l"(acc) : "l"(a), "l"(b));
}

// ============================================================
// Kernel 1: h1 = x @ Wh (fused per-row score dots in epilogue)
// 128x128 tile, 256 threads, 8x8 microtile via FFMA2 (round-8 form).
// ============================================================
__global__ __launch_bounds__(256) void gemm1_kernel(const float* __restrict__ x,
                                                    const float* __restrict__ Wh,
                                                    const float* __restrict__ ah) {
    __shared__ __align__(16) float sxT[16][132];   // [k][row]
    __shared__ __align__(16) float sW[16][132];    // [k][col]
    const int r0 = blockIdx.x * 128;
    const int by = blockIdx.y;
    const int tid = threadIdx.x;
    const int tx = tid & 15, ty = tid >> 4;

    ull acc[8][4] = {};

    float4 px0, px1, pw0, pw1;
    {
        int e0 = tid, e1 = tid + 256;
        int r_ = e0 >> 2, kq = e0 & 3;
        px0 = *(const float4*)&x[(r0 + r_) * NFEAT + kq * 4];
        r_ = e1 >> 2; kq = e1 & 3;
        px1 = *(const float4*)&x[(r0 + r_) * NFEAT + kq * 4];
        int k_ = e0 >> 5, cq = e0 & 31;
        pw0 = *(const float4*)&Wh[((2 * by + (cq >> 4)) * NFEAT + k_) * NHID + (cq & 15) * 4];
        k_ = e1 >> 5; cq = e1 & 31;
        pw1 = *(const float4*)&Wh[((2 * by + (cq >> 4)) * NFEAT + k_) * NHID + (cq & 15) * 4];
    }

    for (int kt = 0; kt < NFEAT / 16; kt++) {
        __syncthreads();
        {
            int e0 = tid, e1 = tid + 256;
            int r_ = e0 >> 2, kq = e0 & 3;
            sxT[kq * 4 + 0][r_] = px0.x; sxT[kq * 4 + 1][r_] = px0.y;
            sxT[kq * 4 + 2][r_] = px0.z; sxT[kq * 4 + 3][r_] = px0.w;
            r_ = e1 >> 2; kq = e1 & 3;
            sxT[kq * 4 + 0][r_] = px1.x; sxT[kq * 4 + 1][r_] = px1.y;
            sxT[kq * 4 + 2][r_] = px1.z; sxT[kq * 4 + 3][r_] = px1.w;
            int k_ = e0 >> 5, cq = e0 & 31;
            *(float4*)&sW[k_][cq * 4] = pw0;
            k_ = e1 >> 5; cq = e1 & 31;
            *(float4*)&sW[k_][cq * 4] = pw1;
        }
        __syncthreads();
        if (kt + 1 < NFEAT / 16) {
            int k0 = (kt + 1) * 16;
            int e0 = tid, e1 = tid + 256;
            int r_ = e0 >> 2, kq = e0 & 3;
            px0 = *(const float4*)&x[(r0 + r_) * NFEAT + k0 + kq * 4];
            r_ = e1 >> 2; kq = e1 & 3;
            px1 = *(const float4*)&x[(r0 + r_) * NFEAT + k0 + kq * 4];
            int k_ = e0 >> 5, cq = e0 & 31;
            pw0 = *(const float4*)&Wh[((2 * by + (cq >> 4)) * NFEAT + k0 + k_) * NHID + (cq & 15) * 4];
            k_ = e1 >> 5; cq = e1 & 31;
            pw1 = *(const float4*)&Wh[((2 * by + (cq >> 4)) * NFEAT + k0 + k_) * NHID + (cq & 15) * 4];
        }
        #pragma unroll
        for (int k = 0; k < 16; k++) {
            float4 a03 = *(const float4*)&sxT[k][ty * 8];
            float4 a47 = *(const float4*)&sxT[k][ty * 8 + 4];
            ulonglong2 bA = *(const ulonglong2*)&sW[k][tx * 8];
            ulonglong2 bB = *(const ulonglong2*)&sW[k][tx * 8 + 4];
            ull pa[8];
            pa[0] = pack_dup(a03.x); pa[1] = pack_dup(a03.y);
            pa[2] = pack_dup(a03.z); pa[3] = pack_dup(a03.w);
            pa[4] = pack_dup(a47.x); pa[5] = pack_dup(a47.y);
            pa[6] = pack_dup(a47.z); pa[7] = pack_dup(a47.w);
            #pragma unroll
            for (int i = 0; i < 8; i++) {
                fma2(acc[i][0], pa[i], bA.x);
                fma2(acc[i][1], pa[i], bA.y);
                fma2(acc[i][2], pa[i], bB.x);
                fma2(acc[i][3], pa[i], bB.y);
            }
        }
    }

    const int head = 2 * by + (tx >> 3);
    const int cb = (tx * 8) & 63;
    float4 as0 = *(const float4*)&ah[head * 2 * NHID + cb];
    float4 as1 = *(const float4*)&ah[head * 2 * NHID + cb + 4];
    float4 ad0 = *(const float4*)&ah[head * 2 * NHID + NHID + cb];
    float4 ad1 = *(const float4*)&ah[head * 2 * NHID + NHID + cb + 4];
    #pragma unroll
    for (int i = 0; i < 8; i++) {
        int r = r0 + ty * 8 + i;
        float4 lo, hi;
        lo.x = __uint_as_float((unsigned)acc[i][0]);  lo.y = __uint_as_float((unsigned)(acc[i][0] >> 32));
        lo.z = __uint_as_float((unsigned)acc[i][1]);  lo.w = __uint_as_float((unsigned)(acc[i][1] >> 32));
        hi.x = __uint_as_float((unsigned)acc[i][2]);  hi.y = __uint_as_float((unsigned)(acc[i][2] >> 32));
        hi.z = __uint_as_float((unsigned)acc[i][3]);  hi.w = __uint_as_float((unsigned)(acc[i][3] >> 32));
        *(float4*)&g_h1[(head * NN + r) * NHID + cb]     = lo;
        *(float4*)&g_h1[(head * NN + r) * NHID + cb + 4] = hi;
        float ss = lo.x*as0.x + lo.y*as0.y + lo.z*as0.z + lo.w*as0.w
                 + hi.x*as1.x + hi.y*as1.y + hi.z*as1.z + hi.w*as1.w;
        float sd = lo.x*ad0.x + lo.y*ad0.y + lo.z*ad0.z + lo.w*ad0.w
                 + hi.x*ad1.x + hi.y*ad1.y + hi.z*ad1.z + hi.w*ad1.w;
        #pragma unroll
        for (int o = 4; o; o >>= 1) {
            ss += __shfl_xor_sync(0xffffffffu, ss, o);
            sd += __shfl_xor_sync(0xffffffffu, sd, o);
        }
        if ((tx & 7) == 0) {
            g_ssrc[head * NN + r] = ss;
            g_sdst[head * NN + r] = sd;
        }
    }
}

// ============================================================
// Bitonic sort (warp-local shfl for j<=16) + fused exp caches
// + fused scalar prefix/suffix scans (es/fs) in the tail.
// ============================================================
__device__ void sortex_body(float* sv, int* si_, float* wtA, float* wtB,
                            const float* __restrict__ src,
                            float* ts, int* pm, float* ea_o, float* eb_o,
                            float* es_, float* fs_) {
    const int tid = threadIdx.x, lane = tid & 31, w = tid >> 5;
    for (int i = tid; i < 4096; i += 1024) { sv[i] = src[i]; si_[i] = i; }
    __syncthreads();

    #pragma unroll
    for (int gg = 0; gg < 4; gg++) {
        int g = w * 4 + gg, i = g * 32 + lane;
        float v = sv[i]; int id = si_[i];
        #pragma unroll
        for (int k = 2; k <= 32; k <<= 1) {
            bool up = ((i & k) == 0);
            #pragma unroll
            for (int j = k >> 1; j; j >>= 1) {
                float ov = __shfl_xor_sync(0xffffffffu, v, j);
                int   oi = __shfl_xor_sync(0xffffffffu, id, j);
                bool lower = (lane & j) == 0;
                bool agtb = lower ? (v > ov) : (ov > v);
                if (agtb == up) { v = ov; id = oi; }
            }
        }
        sv[i] = v; si_[i] = id;
    }
    __syncthreads();

    for (int k = 64; k <= 4096; k <<= 1) {
        for (int j = k >> 1; j >= 32; j >>= 1) {
            #pragma unroll
            for (int q = 0; q < 4; q++) {
                int i = tid + q * 1024;
                int ixj = i ^ j;
                if (ixj > i) {
                    bool up = ((i & k) == 0);
                    float a = sv[i], b = sv[ixj];
                    if ((a > b) == up) {
                        sv[i] = b; sv[ixj] = a;
                        int t = si_[i]; si_[i] = si_[ixj]; si_[ixj] = t;
                    }
                }
            }
            __syncthreads();
        }
        #pragma unroll
        for (int gg = 0; gg < 4; gg++) {
            int g = w * 4 + gg, i = g * 32 + lane;
            float v = sv[i]; int id = si_[i];
            bool up = ((i & k) == 0);
            #pragma unroll
            for (int j = 16; j; j >>= 1) {
                float ov = __shfl_xor_sync(0xffffffffu, v, j);
                int   oi = __shfl_xor_sync(0xffffffffu, id, j);
                bool lower = (lane & j) == 0;
                bool agtb = lower ? (v > ov) : (ov > v);
                if (agtb == up) { v = ov; id = oi; }
            }
            sv[i] = v; si_[i] = id;
        }
        __syncthreads();
    }

    // tail: write sorted arrays + exp caches + scalar scans
    const int base = tid * 4;
    float eaz[4], ebz[4];
    #pragma unroll
    for (int q = 0; q < 4; q++) {
        float t = sv[base + q];
        eaz[q] = __expf(t); ebz[q] = __expf(ALPHA * t);
        ts[base + q] = t; pm[base + q] = si_[base + q];
        ea_o[base + q] = eaz[q]; eb_o[base + q] = ebz[q];
    }
    float sumB = ebz[0] + ebz[1] + ebz[2] + ebz[3];
    float sumA = eaz[0] + eaz[1] + eaz[2] + eaz[3];
    float inclB = sumB;
    #pragma unroll
    for (int o = 1; o < 32; o <<= 1) { float t = __shfl_up_sync(0xffffffffu, inclB, o); if (lane >= o) inclB += t; }
    float sufA = sumA;
    #pragma unroll
    for (int o = 1; o < 32; o <<= 1) { float t = __shfl_down_sync(0xffffffffu, sufA, o); if (lane + o < 32) sufA += t; }
    if (lane == 31) wtB[w] = inclB;
    if (lane == 0)  wtA[w] = sufA;
    __syncthreads();
    float prevB = 0.f, aftA = 0.f;
    for (int ww = 0; ww < 32; ww++) { if (ww < w) prevB += wtB[ww]; if (ww > w) aftA += wtA[ww]; }
    float exB = prevB + inclB - sumB;
    float sfA = aftA + sufA;
    #pragma unroll
    for (int q = 0; q < 4; q++) {
        fs_[base + q] = exB;
        es_[base + q] = sfA;
        exB += ebz[q];
        sfA -= eaz[q];
    }
    if (tid == 1023) { fs_[4096] = exB; es_[4096] = 0.f; }
}

__global__ __launch_bounds__(1024) void sort1_kernel() {
    __shared__ float sv[4096]; __shared__ int si_[4096];
    __shared__ float wtA[32], wtB[32];
    const int h = blockIdx.x;
    if (threadIdx.x == 0) g_cnt1[h] = 0;   // reset last-block counter (graph-replay safe)
    sortex_body(sv, si_, wtA, wtB, g_sdst + h * NN, g_ts1 + h * NN, g_pm1 + h * NN,
                g_e1a + h * NN, g_e1b + h * NN, g_es1 + h * NP1, g_fs1 + h * NP1);
}
__global__ __launch_bounds__(1024) void sort2_kernel() {
    __shared__ float sv[4096]; __shared__ int si_[4096];
    __shared__ float wtA[32], wtB[32];
    sortex_body(sv, si_, wtA, wtB, g_s2dst, g_ts2, g_pm2, g_e2a, g_e2b, g_es2, g_fs2);
}

// ============================================================
// scan1: rank-tile blocks, 2-pass gather (E via tile-total minus
// running prefix), coalesced [r][c] E/F. FUSED cross-tile offsets:
// last finishing block per head computes offE/offF (kills off1).
// ============================================================
__global__ void scan1_kernel() {
    const int h  = blockIdx.y;
    const int tt = blockIdx.x;
    const int tid = threadIdx.x;
    const int c = tid & 63, sub = tid >> 6;
    const int kb = tt * TILE + sub * 32;
    const int hb = h * NN;
    __shared__ float sA[4][64], sB[4][64];
    __shared__ unsigned int isLast;

    // pass 1: sub totals
    float aT = 0.f, bT = 0.f;
    #pragma unroll 4
    for (int m = 0; m < 32; m++) {
        int idx = kb + m;
        float hv = g_h1[(hb + g_pm1[hb + idx]) * NHID + c];
        aT += g_e1a[hb + idx] * hv;
        bT += g_e1b[hb + idx] * hv;
    }
    sA[sub][c] = aT; sB[sub][c] = bT;
    __syncthreads();
    float offb = 0.f, offa = 0.f;
    #pragma unroll
    for (int s = 0; s < 4; s++) { if (s < sub) offb += sB[s][c]; if (s > sub) offa += sA[s][c]; }

    // pass 2: write F (prefix) and E (suffix = total - prefix) in one gather
    float fb = offb, pa = 0.f;
    #pragma unroll 4
    for (int m = 0; m < 32; m++) {
        int idx = kb + m;
        float hv = g_h1[(hb + g_pm1[hb + idx]) * NHID + c];
        float prA = g_e1a[hb + idx] * hv;
        float prB = g_e1b[hb + idx] * hv;
        g_F1[(h * NP1 + idx) * NHID + c] = fb;
        g_E1[(h * NP1 + idx) * NHID + c] = offa + (aT - pa);
        fb += prB;
        pa += prA;
    }
    if (sub == 0) {
        g_totA[(h * NT + tt) * NHID + c] = sA[0][c] + sA[1][c] + sA[2][c] + sA[3][c];
        g_totB[(h * NT + tt) * NHID + c] = sB[0][c] + sB[1][c] + sB[2][c] + sB[3][c];
    }
    __threadfence();
    __syncthreads();
    if (tid == 0) isLast = (atomicAdd(&g_cnt1[h], 1u) == NT - 1);
    __syncthreads();
    if (isLast) {
        // this block is the last for head h: all totals visible. Compute
        // cross-tile offsets: warp w handles cols 8w..8w+7, lane = tile.
        const int w = tid >> 5, lane = tid & 31;
        #pragma unroll
        for (int cc = 0; cc < 8; cc++) {
            const int col = w * 8 + cc;
            const float a = g_totA[(h * NT + lane) * NHID + col];
            const float b = g_totB[(h * NT + lane) * NHID + col];
            float ib = b;
            #pragma unroll
            for (int o = 1; o < 32; o <<= 1) {
                float t = __shfl_up_sync(0xffffffffu, ib, o);
                if (lane >= o) ib += t;
            }
            float sa = a;
            #pragma unroll
            for (int o = 1; o < 32; o <<= 1) {
                float t = __shfl_down_sync(0xffffffffu, sa, o);
                if (lane + o < 32) sa += t;
            }
            g_offF[(h * (NT + 1) + lane) * NHID + col] = ib - b;
            g_offE[(h * (NT + 1) + lane) * NHID + col] = sa - a;
            if (lane == 31) {
                g_offF[(h * (NT + 1) + NT) * NHID + col] = ib;
                g_offE[(h * (NT + 1) + NT) * NHID + col] = 0.f;
            }
            if (lane == 0) {
                g_E1[(h * NP1 + NN) * NHID + col] = 0.f;
                g_F1[(h * NP1 + NN) * NHID + col] = 0.f;
            }
        }
    }
}

// ============================================================
// row1: parallel-lane binary searches, batched gathers -> xc.
// ============================================================
__global__ void row1_kernel() {
    __shared__ float st[4096];
    const int h = blockIdx.y;
    const int warp = threadIdx.x >> 5, lane = threadIdx.x & 31;
    for (int q = threadIdx.x; q < 4096; q += 256) st[q] = g_ts1[h * NN + q];
    __syncthreads();
    const int rbase = blockIdx.x * 64 + warp * 8;
    const float s_l = g_ssrc[h * NN + rbase + (lane & 7)];
    const float w1_l = __expf(s_l), w2_l = __expf(ALPHA * s_l);
    int lo = 0, hi = 4096; const float thr = -s_l;
    while (lo < hi) { int mid = (lo + hi) >> 1; if (st[mid] <= thr) lo = mid + 1; else hi = mid; }

    #pragma unroll
    for (int half = 0; half < 2; half++) {
        int rA[4]; float w1A[4], w2A[4];
        #pragma unroll
        for (int q = 0; q < 4; q++) {
            int rr = half * 4 + q;
            rA[q]  = __shfl_sync(0xffffffffu, lo, rr);
            w1A[q] = __shfl_sync(0xffffffffu, w1_l, rr);
            w2A[q] = __shfl_sync(0xffffffffu, w2_l, rr);
        }
        float e0[4], e1v[4], f0[4], f1v[4], oe0[4], oe1[4], of0[4], of1[4], dn1[4], dn2[4];
        #pragma unroll
        for (int q = 0; q < 4; q++) {
            int r = rA[q], tt = r >> 7;
            const float* E  = &g_E1[(h * NP1 + r) * NHID];
            const float* F  = &g_F1[(h * NP1 + r) * NHID];
            const float* OE = &g_offE[(h * (NT + 1) + tt) * NHID];
            const float* OF = &g_offF[(h * (NT + 1) + tt) * NHID];
            e0[q] = E[lane];  e1v[q] = E[lane + 32];
            f0[q] = F[lane];  f1v[q] = F[lane + 32];
            oe0[q] = OE[lane]; oe1[q] = OE[lane + 32];
            of0[q] = OF[lane]; of1[q] = OF[lane + 32];
            dn1[q] = g_es1[h * NP1 + r]; dn2[q] = g_fs1[h * NP1 + r];
        }
        #pragma unroll
        for (int q = 0; q < 4; q++) {
            int i = rbase + half * 4 + q;
            float inv = 1.f / (w1A[q] * dn1[q] + w2A[q] * dn2[q]);
            float va = (w1A[q] * (e0[q]  + oe0[q]) + w2A[q] * (f0[q]  + of0[q])) * inv;
            float vb = (w1A[q] * (e1v[q] + oe1[q]) + w2A[q] * (f1v[q] + of1[q])) * inv;
            g_xc[i * (NH * NHID) + h * NHID + lane]      = elu1(va);
            g_xc[i * (NH * NHID) + h * NHID + lane + 32] = elu1(vb);
        }
    }
}

// ============================================================
// gemm2: h2 = xc @ Wo + layer-2 score dots
// ============================================================
__global__ void gemm2_kernel(const float* __restrict__ Wo, const float* __restrict__ ao) {
    __shared__ __align__(16) float sxcT[32][68];
    __shared__ __align__(16) float sWo[32][20];
    __shared__ __align__(16) float sh2s[64][17];
    const int r0 = blockIdx.x * 64;
    const int tid = threadIdx.x;
    const int c4 = tid & 3, r = tid >> 2;
    float acc[4] = {};

    for (int k0 = 0; k0 < NFEAT; k0 += 32) {
        __syncthreads();
        #pragma unroll
        for (int i = tid; i < 2048; i += 256) {
            int k = i & 31, rr = i >> 5;
            sxcT[k][rr] = g_xc[(r0 + rr) * NFEAT + k0 + k];
        }
        #pragma unroll
        for (int i = tid; i < 512; i += 256) {
            int k = i >> 4, c = i & 15;
            sWo[k][c] = Wo[(k0 + k) * NCLS + c];
        }
        __syncthreads();
        #pragma unroll
        for (int k = 0; k < 32; k++) {
            float a = sxcT[k][r];
            float4 b = *(const float4*)&sWo[k][c4 * 4];
            acc[0] += a * b.x; acc[1] += a * b.y; acc[2] += a * b.z; acc[3] += a * b.w;
        }
    }
    *(float4*)&g_h2[(r0 + r) * NCLS + c4 * 4] = make_float4(acc[0], acc[1], acc[2], acc[3]);
    sh2s[r][c4 * 4 + 0] = acc[0];
    sh2s[r][c4 * 4 + 1] = acc[1];
    sh2s[r][c4 * 4 + 2] = acc[2];
    sh2s[r][c4 * 4 + 3] = acc[3];
    __syncthreads();
    if (tid < 64) {
        float ss = 0.f, sd = 0.f;
        #pragma unroll
        for (int c = 0; c < NCLS; c++) {
            float hv = sh2s[tid][c];
            ss += hv * ao[c];
            sd += hv * ao[NCLS + c];
        }
        g_s2src[r0 + tid] = ss;
        g_s2dst[r0 + tid] = sd;
    }
}

// ============================================================
// scan2: per-column scans for layer 2
// ============================================================
__device__ __forceinline__ void chunk_offsets(const float* totA, const float* totB,
                                              float* offA, float* offB, int tid) {
    if (tid < 32) {
        float pb[8], pa[8];
        float sb = 0.f, sa = 0.f;
        #pragma unroll
        for (int j = 0; j < 8; j++) { sb += totB[tid * 8 + j]; pb[j] = sb; }
        #pragma unroll
        for (int j = 7; j >= 0; j--) { sa += totA[tid * 8 + j]; pa[j] = sa; }
        float eb = sb;
        #pragma unroll
        for (int o = 1; o < 32; o <<= 1) {
            float t = __shfl_up_sync(0xffffffffu, eb, o);
            if (tid >= o) eb += t;
        }
        eb -= sb;
        float ea = sa;
        #pragma unroll
        for (int o = 1; o < 32; o <<= 1) {
            float t = __shfl_down_sync(0xffffffffu, ea, o);
            if (tid + o < 32) ea += t;
        }
        ea -= sa;
        #pragma unroll
        for (int j = 0; j < 8; j++) {
            offB[tid * 8 + j + 1] = eb + pb[j];
            offA[tid * 8 + j]     = ea + pa[j];
        }
        if (tid == 0)  offB[0]   = 0.f;
        if (tid == 31) offA[256] = 0.f;
    }
}

__global__ void scan2_kernel() {
    const int c = blockIdx.x;
    const int tid = threadIdx.x;
    __shared__ float totA[256], totB[256];
    __shared__ float offA[257], offB[257];
    float a_loc[16], b_loc[16];
    const int base = tid * 16;
    #pragma unroll
    for (int q = 0; q < 16; q++) {
        int k = base + q;
        float hv = g_h2[g_pm2[k] * NCLS + c];
        a_loc[q] = g_e2a[k] * hv;
        b_loc[q] = g_e2b[k] * hv;
    }
    #pragma unroll
    for (int q = 1; q < 16; q++) b_loc[q] += b_loc[q - 1];
    #pragma unroll
    for (int q = 14; q >= 0; q--) a_loc[q] += a_loc[q + 1];
    totB[tid] = b_loc[15]; totA[tid] = a_loc[0];
    __syncthreads();
    chunk_offsets(totA, totB, offA, offB, tid);
    __syncthreads();
    const float ob = offB[tid];
    const float oa = offA[tid + 1];
    float* E = g_E2 + c;
    float* F = g_F2 + c;
    #pragma unroll
    for (int q = 0; q < 16; q++) {
        E[(base + q) * NCLS]     = a_loc[q] + oa;
        F[(base + q + 1) * NCLS] = b_loc[q] + ob;
    }
    if (tid == 0)   F[0] = 0.f;
    if (tid == 255) E[NN * NCLS] = 0.f;
}

// ============================================================
// row2: parallel-lane searches + combine + elu + log_softmax
// ============================================================
__global__ void row2_kernel(float* __restrict__ out) {
    __shared__ float st[4096];
    const int warp = threadIdx.x >> 5, lane = threadIdx.x & 31;
    for (int q = threadIdx.x; q < 4096; q += 256) st[q] = g_ts2[q];
    __syncthreads();
    const int rbase = blockIdx.x * 64 + warp * 8;
    const float s_l = g_s2src[rbase + (lane & 7)];
    const float w1_l = __expf(s_l), w2_l = __expf(ALPHA * s_l);
    int lo = 0, hi = 4096; const float thr = -s_l;
    while (lo < hi) { int mid = (lo + hi) >> 1; if (st[mid] <= thr) lo = mid + 1; else hi = mid; }

    #pragma unroll
    for (int rr = 0; rr < 8; rr++) {
        const int i = rbase + rr;
        const int r  = __shfl_sync(0xffffffffu, lo, rr);
        const float w1 = __shfl_sync(0xffffffffu, w1_l, rr);
        const float w2 = __shfl_sync(0xffffffffu, w2_l, rr);
        const float den = w1 * g_es2[r] + w2 * g_fs2[r];
        const float invden = 1.f / den;
        float v = -1e30f;
        if (lane < NCLS)
            v = elu1((w1 * g_E2[r * NCLS + lane] + w2 * g_F2[r * NCLS + lane]) * invden);
        float m = v;
        #pragma unroll
        for (int o = 8; o; o >>= 1) m = fmaxf(m, __shfl_xor_sync(0xffffffffu, m, o));
        float s = __expf(v - m);
        #pragma unroll
        for (int o = 8; o; o >>= 1) s += __shfl_xor_sync(0xffffffffu, s, o);
        const float lse = m + __logf(s);
        if (lane < NCLS) out[i * NCLS + lane] = v - lse;
    }
}

// ============================================================
extern "C" void kernel_launch(void* const* d_in, const int* in_sizes, int n_in,
                              void* d_out, int out_size) {
    const float* x  = (const float*)d_in[0];
    const float* Wh = (const float*)d_in[1];
    const float* ah = (const float*)d_in[2];
    const float* Wo = (const float*)d_in[3];
    const float* ao = (const float*)d_in[4];
    float* out = (float*)d_out;

    gemm1_kernel<<<dim3(NN / 128, 4), 256>>>(x, Wh, ah);
    sort1_kernel<<<NH, 1024>>>();
    scan1_kernel<<<dim3(NT, NH), 256>>>();
    row1_kernel<<<dim3(NN / 64, NH), 256>>>();
    gemm2_kernel<<<NN / 64, 256>>>(Wo, ao);
    sort2_kernel<<<1, 1024>>>();
    scan2_kernel<<<NCLS, 256>>>();
    row2_kernel<<<NN / 64, 256>>>(out);
}

// round 15
// speedup vs baseline: 1.0720x; 1.0219x over previous
#include <cuda_runtime.h>
#include <cstdint>

#define NN    4096
#define NP1   4097
#define NFEAT 512
#define NHID  64
#define NCLS  16
#define NH    8
#define ALPHA 0.2f
#define TILE  128
#define NT    (NN / TILE)   // 32

typedef unsigned long long ull;

// ---- scratch (device globals; no allocation allowed) ----
__device__ __align__(16) float g_h1[NH * NN * NHID];
__device__ float g_ssrc[NH * NN];
__device__ float g_sdst[NH * NN];
__device__ __align__(16) float g_xc[NN * NH * NHID];
__device__ __align__(16) float g_h2[NN * NCLS];
__device__ float g_s2src[NN];
__device__ float g_s2dst[NN];

// sorted scores + permutations + exp caches (written by sort tails)
__device__ float g_ts1[NH * NN];
__device__ int   g_pm1[NH * NN];
__device__ float g_e1a[NH * NN];
__device__ float g_e1b[NH * NN];
__device__ float g_ts2[NN];
__device__ int   g_pm2[NN];
__device__ float g_e2a[NN];
__device__ float g_e2b[NN];

// layer-1 scans, [h][r][c] row-contiguous; within-tile values + cross-tile offsets
__device__ __align__(16) float g_E1[NH * NP1 * NHID];
__device__ __align__(16) float g_F1[NH * NP1 * NHID];
__device__ float g_totA[NH * NT * NHID];
__device__ float g_totB[NH * NT * NHID];
__device__ float g_offE[NH * (NT + 1) * NHID];
__device__ float g_offF[NH * (NT + 1) * NHID];
__device__ float g_es1[NH * NP1];
__device__ float g_fs1[NH * NP1];
__device__ unsigned int g_cnt1[NH];   // last-block counters (reset by sort1)

// layer-2 scans
__device__ float g_E2[NP1 * NCLS];
__device__ float g_F2[NP1 * NCLS];
__device__ float g_es2[NP1];
__device__ float g_fs2[NP1];

__device__ __forceinline__ float elu1(float v) { return v > 0.f ? v : __expf(v) - 1.f; }

// packed f32x2 helpers (sm_103a FFMA2 path)
// pack_dup is an ALU-pipe MOV that dual-issues alongside fma-pipe FFMA2 —
// keeping it in the mainloop is CHEAPER than pre-duplicating in smem
// (which costs +50% LDS/MIO traffic; measured regression in round 10).
__device__ __forceinline__ ull pack_dup(float a) {
    ull r;
    asm("mov.b64 %0, {%1, %1};" : "=l"(r) : "r"(__float_as_uint(a)));
    return r;
}
__device__ __forceinline__ void fma2(ull& acc, ull a, ull b) {
    asm("fma.rn.f32x2 %0, %1, %2, %0;" : "+l"(acc) : "l"(a), "l"(b));
}

// ============================================================
// Kernel 1: h1 = x @ Wh (fused per-row score dots in epilogue)
// 128x128 tile, 256 threads, 8x8 microtile via FFMA2 (round-8 form).
// ============================================================
__global__ __launch_bounds__(256) void gemm1_kernel(const float* __restrict__ x,
                                                    const float* __restrict__ Wh,
                                                    const float* __restrict__ ah) {
    __shared__ __align__(16) float sxT[16][132];   // [k][row]
    __shared__ __align__(16) float sW[16][132];    // [k][col]
    const int r0 = blockIdx.x * 128;
    const int by = blockIdx.y;
    const int tid = threadIdx.x;
    const int tx = tid & 15, ty = tid >> 4;

    ull acc[8][4] = {};

    float4 px0, px1, pw0, pw1;
    {
        int e0 = tid, e1 = tid + 256;
        int r_ = e0 >> 2, kq = e0 & 3;
        px0 = *(const float4*)&x[(r0 + r_) * NFEAT + kq * 4];
        r_ = e1 >> 2; kq = e1 & 3;
        px1 = *(const float4*)&x[(r0 + r_) * NFEAT + kq * 4];
        int k_ = e0 >> 5, cq = e0 & 31;
        pw0 = *(const float4*)&Wh[((2 * by + (cq >> 4)) * NFEAT + k_) * NHID + (cq & 15) * 4];
        k_ = e1 >> 5; cq = e1 & 31;
        pw1 = *(const float4*)&Wh[((2 * by + (cq >> 4)) * NFEAT + k_) * NHID + (cq & 15) * 4];
    }

    for (int kt = 0; kt < NFEAT / 16; kt++) {
        __syncthreads();
        {
            int e0 = tid, e1 = tid + 256;
            int r_ = e0 >> 2, kq = e0 & 3;
            sxT[kq * 4 + 0][r_] = px0.x; sxT[kq * 4 + 1][r_] = px0.y;
            sxT[kq * 4 + 2][r_] = px0.z; sxT[kq * 4 + 3][r_] = px0.w;
            r_ = e1 >> 2; kq = e1 & 3;
            sxT[kq * 4 + 0][r_] = px1.x; sxT[kq * 4 + 1][r_] = px1.y;
            sxT[kq * 4 + 2][r_] = px1.z; sxT[kq * 4 + 3][r_] = px1.w;
            int k_ = e0 >> 5, cq = e0 & 31;
            *(float4*)&sW[k_][cq * 4] = pw0;
            k_ = e1 >> 5; cq = e1 & 31;
            *(float4*)&sW[k_][cq * 4] = pw1;
        }
        __syncthreads();
        if (kt + 1 < NFEAT / 16) {
            int k0 = (kt + 1) * 16;
            int e0 = tid, e1 = tid + 256;
            int r_ = e0 >> 2, kq = e0 & 3;
            px0 = *(const float4*)&x[(r0 + r_) * NFEAT + k0 + kq * 4];
            r_ = e1 >> 2; kq = e1 & 3;
            px1 = *(const float4*)&x[(r0 + r_) * NFEAT + k0 + kq * 4];
            int k_ = e0 >> 5, cq = e0 & 31;
            pw0 = *(const float4*)&Wh[((2 * by + (cq >> 4)) * NFEAT + k0 + k_) * NHID + (cq & 15) * 4];
            k_ = e1 >> 5; cq = e1 & 31;
            pw1 = *(const float4*)&Wh[((2 * by + (cq >> 4)) * NFEAT + k0 + k_) * NHID + (cq & 15) * 4];
        }
        #pragma unroll
        for (int k = 0; k < 16; k++) {
            float4 a03 = *(const float4*)&sxT[k][ty * 8];
            float4 a47 = *(const float4*)&sxT[k][ty * 8 + 4];
            ulonglong2 bA = *(const ulonglong2*)&sW[k][tx * 8];
            ulonglong2 bB = *(const ulonglong2*)&sW[k][tx * 8 + 4];
            ull pa[8];
            pa[0] = pack_dup(a03.x); pa[1] = pack_dup(a03.y);
            pa[2] = pack_dup(a03.z); pa[3] = pack_dup(a03.w);
            pa[4] = pack_dup(a47.x); pa[5] = pack_dup(a47.y);
            pa[6] = pack_dup(a47.z); pa[7] = pack_dup(a47.w);
            #pragma unroll
            for (int i = 0; i < 8; i++) {
                fma2(acc[i][0], pa[i], bA.x);
                fma2(acc[i][1], pa[i], bA.y);
                fma2(acc[i][2], pa[i], bB.x);
                fma2(acc[i][3], pa[i], bB.y);
            }
        }
    }

    const int head = 2 * by + (tx >> 3);
    const int cb = (tx * 8) & 63;
    float4 as0 = *(const float4*)&ah[head * 2 * NHID + cb];
    float4 as1 = *(const float4*)&ah[head * 2 * NHID + cb + 4];
    float4 ad0 = *(const float4*)&ah[head * 2 * NHID + NHID + cb];
    float4 ad1 = *(const float4*)&ah[head * 2 * NHID + NHID + cb + 4];
    #pragma unroll
    for (int i = 0; i < 8; i++) {
        int r = r0 + ty * 8 + i;
        float4 lo, hi;
        lo.x = __uint_as_float((unsigned)acc[i][0]);  lo.y = __uint_as_float((unsigned)(acc[i][0] >> 32));
        lo.z = __uint_as_float((unsigned)acc[i][1]);  lo.w = __uint_as_float((unsigned)(acc[i][1] >> 32));
        hi.x = __uint_as_float((unsigned)acc[i][2]);  hi.y = __uint_as_float((unsigned)(acc[i][2] >> 32));
        hi.z = __uint_as_float((unsigned)acc[i][3]);  hi.w = __uint_as_float((unsigned)(acc[i][3] >> 32));
        *(float4*)&g_h1[(head * NN + r) * NHID + cb]     = lo;
        *(float4*)&g_h1[(head * NN + r) * NHID + cb + 4] = hi;
        float ss = lo.x*as0.x + lo.y*as0.y + lo.z*as0.z + lo.w*as0.w
                 + hi.x*as1.x + hi.y*as1.y + hi.z*as1.z + hi.w*as1.w;
        float sd = lo.x*ad0.x + lo.y*ad0.y + lo.z*ad0.z + lo.w*ad0.w
                 + hi.x*ad1.x + hi.y*ad1.y + hi.z*ad1.z + hi.w*ad1.w;
        #pragma unroll
        for (int o = 4; o; o >>= 1) {
            ss += __shfl_xor_sync(0xffffffffu, ss, o);
            sd += __shfl_xor_sync(0xffffffffu, sd, o);
        }
        if ((tx & 7) == 0) {
            g_ssrc[head * NN + r] = ss;
            g_sdst[head * NN + r] = sd;
        }
    }
}

// ============================================================
// Bitonic sort (warp-local shfl for j<=16) + fused exp caches
// + fused scalar prefix/suffix scans (es/fs) in the tail.
// ============================================================
__device__ void sortex_body(float* sv, int* si_, float* wtA, float* wtB,
                            const float* __restrict__ src,
                            float* ts, int* pm, float* ea_o, float* eb_o,
                            float* es_, float* fs_) {
    const int tid = threadIdx.x, lane = tid & 31, w = tid >> 5;
    for (int i = tid; i < 4096; i += 1024) { sv[i] = src[i]; si_[i] = i; }
    __syncthreads();

    #pragma unroll
    for (int gg = 0; gg < 4; gg++) {
        int g = w * 4 + gg, i = g * 32 + lane;
        float v = sv[i]; int id = si_[i];
        #pragma unroll
        for (int k = 2; k <= 32; k <<= 1) {
            bool up = ((i & k) == 0);
            #pragma unroll
            for (int j = k >> 1; j; j >>= 1) {
                float ov = __shfl_xor_sync(0xffffffffu, v, j);
                int   oi = __shfl_xor_sync(0xffffffffu, id, j);
                bool lower = (lane & j) == 0;
                bool agtb = lower ? (v > ov) : (ov > v);
                if (agtb == up) { v = ov; id = oi; }
            }
        }
        sv[i] = v; si_[i] = id;
    }
    __syncthreads();

    for (int k = 64; k <= 4096; k <<= 1) {
        for (int j = k >> 1; j >= 32; j >>= 1) {
            #pragma unroll
            for (int q = 0; q < 4; q++) {
                int i = tid + q * 1024;
                int ixj = i ^ j;
                if (ixj > i) {
                    bool up = ((i & k) == 0);
                    float a = sv[i], b = sv[ixj];
                    if ((a > b) == up) {
                        sv[i] = b; sv[ixj] = a;
                        int t = si_[i]; si_[i] = si_[ixj]; si_[ixj] = t;
                    }
                }
            }
            __syncthreads();
        }
        #pragma unroll
        for (int gg = 0; gg < 4; gg++) {
            int g = w * 4 + gg, i = g * 32 + lane;
            float v = sv[i]; int id = si_[i];
            bool up = ((i & k) == 0);
            #pragma unroll
            for (int j = 16; j; j >>= 1) {
                float ov = __shfl_xor_sync(0xffffffffu, v, j);
                int   oi = __shfl_xor_sync(0xffffffffu, id, j);
                bool lower = (lane & j) == 0;
                bool agtb = lower ? (v > ov) : (ov > v);
                if (agtb == up) { v = ov; id = oi; }
            }
            sv[i] = v; si_[i] = id;
        }
        __syncthreads();
    }

    // tail: write sorted arrays + exp caches + scalar scans
    const int base = tid * 4;
    float eaz[4], ebz[4];
    #pragma unroll
    for (int q = 0; q < 4; q++) {
        float t = sv[base + q];
        eaz[q] = __expf(t); ebz[q] = __expf(ALPHA * t);
        ts[base + q] = t; pm[base + q] = si_[base + q];
        ea_o[base + q] = eaz[q]; eb_o[base + q] = ebz[q];
    }
    float sumB = ebz[0] + ebz[1] + ebz[2] + ebz[3];
    float sumA = eaz[0] + eaz[1] + eaz[2] + eaz[3];
    float inclB = sumB;
    #pragma unroll
    for (int o = 1; o < 32; o <<= 1) { float t = __shfl_up_sync(0xffffffffu, inclB, o); if (lane >= o) inclB += t; }
    float sufA = sumA;
    #pragma unroll
    for (int o = 1; o < 32; o <<= 1) { float t = __shfl_down_sync(0xffffffffu, sufA, o); if (lane + o < 32) sufA += t; }
    if (lane == 31) wtB[w] = inclB;
    if (lane == 0)  wtA[w] = sufA;
    __syncthreads();
    float prevB = 0.f, aftA = 0.f;
    for (int ww = 0; ww < 32; ww++) { if (ww < w) prevB += wtB[ww]; if (ww > w) aftA += wtA[ww]; }
    float exB = prevB + inclB - sumB;
    float sfA = aftA + sufA;
    #pragma unroll
    for (int q = 0; q < 4; q++) {
        fs_[base + q] = exB;
        es_[base + q] = sfA;
        exB += ebz[q];
        sfA -= eaz[q];
    }
    if (tid == 1023) { fs_[4096] = exB; es_[4096] = 0.f; }
}

__global__ __launch_bounds__(1024) void sort1_kernel() {
    __shared__ float sv[4096]; __shared__ int si_[4096];
    __shared__ float wtA[32], wtB[32];
    const int h = blockIdx.x;
    if (threadIdx.x == 0) g_cnt1[h] = 0;   // reset last-block counter (graph-replay safe)
    sortex_body(sv, si_, wtA, wtB, g_sdst + h * NN, g_ts1 + h * NN, g_pm1 + h * NN,
                g_e1a + h * NN, g_e1b + h * NN, g_es1 + h * NP1, g_fs1 + h * NP1);
}
__global__ __launch_bounds__(1024) void sort2_kernel() {
    __shared__ float sv[4096]; __shared__ int si_[4096];
    __shared__ float wtA[32], wtB[32];
    sortex_body(sv, si_, wtA, wtB, g_s2dst, g_ts2, g_pm2, g_e2a, g_e2b, g_es2, g_fs2);
}

// ============================================================
// scan1: rank-tile blocks, 2-pass gather (E via tile-total minus
// running prefix), coalesced [r][c] E/F. FUSED cross-tile offsets:
// last finishing block per head computes offE/offF. The gpu-scope
// fence is restricted to the sub==0 threads that write totA/totB
// (E/F stores are consumed only across the kernel boundary).
// ============================================================
__global__ void scan1_kernel() {
    const int h  = blockIdx.y;
    const int tt = blockIdx.x;
    const int tid = threadIdx.x;
    const int c = tid & 63, sub = tid >> 6;
    const int kb = tt * TILE + sub * 32;
    const int hb = h * NN;
    __shared__ float sA[4][64], sB[4][64];
    __shared__ unsigned int isLast;

    // pass 1: sub totals
    float aT = 0.f, bT = 0.f;
    #pragma unroll 4
    for (int m = 0; m < 32; m++) {
        int idx = kb + m;
        float hv = g_h1[(hb + g_pm1[hb + idx]) * NHID + c];
        aT += g_e1a[hb + idx] * hv;
        bT += g_e1b[hb + idx] * hv;
    }
    sA[sub][c] = aT; sB[sub][c] = bT;
    __syncthreads();
    float offb = 0.f, offa = 0.f;
    #pragma unroll
    for (int s = 0; s < 4; s++) { if (s < sub) offb += sB[s][c]; if (s > sub) offa += sA[s][c]; }

    // pass 2: write F (prefix) and E (suffix = total - prefix) in one gather
    float fb = offb, pa = 0.f;
    #pragma unroll 4
    for (int m = 0; m < 32; m++) {
        int idx = kb + m;
        float hv = g_h1[(hb + g_pm1[hb + idx]) * NHID + c];
        float prA = g_e1a[hb + idx] * hv;
        float prB = g_e1b[hb + idx] * hv;
        g_F1[(h * NP1 + idx) * NHID + c] = fb;
        g_E1[(h * NP1 + idx) * NHID + c] = offa + (aT - pa);
        fb += prB;
        pa += prA;
    }
    if (sub == 0) {
        g_totA[(h * NT + tt) * NHID + c] = sA[0][c] + sA[1][c] + sA[2][c] + sA[3][c];
        g_totB[(h * NT + tt) * NHID + c] = sB[0][c] + sB[1][c] + sB[2][c] + sB[3][c];
        __threadfence();   // order totA/totB before the counter bump (writers only)
    }
    __syncthreads();
    if (tid == 0) isLast = (atomicAdd(&g_cnt1[h], 1u) == NT - 1);
    __syncthreads();
    if (isLast) {
        // this block is the last for head h: all totals visible. Compute
        // cross-tile offsets: warp w handles cols 8w..8w+7, lane = tile.
        const int w = tid >> 5, lane = tid & 31;
        #pragma unroll
        for (int cc = 0; cc < 8; cc++) {
            const int col = w * 8 + cc;
            const float a = g_totA[(h * NT + lane) * NHID + col];
            const float b = g_totB[(h * NT + lane) * NHID + col];
            float ib = b;
            #pragma unroll
            for (int o = 1; o < 32; o <<= 1) {
                float t = __shfl_up_sync(0xffffffffu, ib, o);
                if (lane >= o) ib += t;
            }
            float sa = a;
            #pragma unroll
            for (int o = 1; o < 32; o <<= 1) {
                float t = __shfl_down_sync(0xffffffffu, sa, o);
                if (lane + o < 32) sa += t;
            }
            g_offF[(h * (NT + 1) + lane) * NHID + col] = ib - b;
            g_offE[(h * (NT + 1) + lane) * NHID + col] = sa - a;
            if (lane == 31) {
                g_offF[(h * (NT + 1) + NT) * NHID + col] = ib;
                g_offE[(h * (NT + 1) + NT) * NHID + col] = 0.f;
            }
            if (lane == 0) {
                g_E1[(h * NP1 + NN) * NHID + col] = 0.f;
                g_F1[(h * NP1 + NN) * NHID + col] = 0.f;
            }
        }
    }
}

// ============================================================
// row1: 128 rows per block (512 threads, 16 warps) — halves the
// per-block 16KB table-load amortization vs 64-row blocks and
// doubles latency overlap. Parallel-lane searches + batched gathers.
// ============================================================
__global__ __launch_bounds__(512) void row1_kernel() {
    __shared__ float st[4096];
    const int h = blockIdx.y;
    const int warp = threadIdx.x >> 5, lane = threadIdx.x & 31;
    for (int q = threadIdx.x; q < 4096; q += 512) st[q] = g_ts1[h * NN + q];
    __syncthreads();
    const int rbase = blockIdx.x * 128 + warp * 8;
    const float s_l = g_ssrc[h * NN + rbase + (lane & 7)];
    const float w1_l = __expf(s_l), w2_l = __expf(ALPHA * s_l);
    int lo = 0, hi = 4096; const float thr = -s_l;
    while (lo < hi) { int mid = (lo + hi) >> 1; if (st[mid] <= thr) lo = mid + 1; else hi = mid; }

    #pragma unroll
    for (int half = 0; half < 2; half++) {
        int rA[4]; float w1A[4], w2A[4];
        #pragma unroll
        for (int q = 0; q < 4; q++) {
            int rr = half * 4 + q;
            rA[q]  = __shfl_sync(0xffffffffu, lo, rr);
            w1A[q] = __shfl_sync(0xffffffffu, w1_l, rr);
            w2A[q] = __shfl_sync(0xffffffffu, w2_l, rr);
        }
        float e0[4], e1v[4], f0[4], f1v[4], oe0[4], oe1[4], of0[4], of1[4], dn1[4], dn2[4];
        #pragma unroll
        for (int q = 0; q < 4; q++) {
            int r = rA[q], tt = r >> 7;
            const float* E  = &g_E1[(h * NP1 + r) * NHID];
            const float* F  = &g_F1[(h * NP1 + r) * NHID];
            const float* OE = &g_offE[(h * (NT + 1) + tt) * NHID];
            const float* OF = &g_offF[(h * (NT + 1) + tt) * NHID];
            e0[q] = E[lane];  e1v[q] = E[lane + 32];
            f0[q] = F[lane];  f1v[q] = F[lane + 32];
            oe0[q] = OE[lane]; oe1[q] = OE[lane + 32];
            of0[q] = OF[lane]; of1[q] = OF[lane + 32];
            dn1[q] = g_es1[h * NP1 + r]; dn2[q] = g_fs1[h * NP1 + r];
        }
        #pragma unroll
        for (int q = 0; q < 4; q++) {
            int i = rbase + half * 4 + q;
            float inv = 1.f / (w1A[q] * dn1[q] + w2A[q] * dn2[q]);
            float va = (w1A[q] * (e0[q]  + oe0[q]) + w2A[q] * (f0[q]  + of0[q])) * inv;
            float vb = (w1A[q] * (e1v[q] + oe1[q]) + w2A[q] * (f1v[q] + of1[q])) * inv;
            g_xc[i * (NH * NHID) + h * NHID + lane]      = elu1(va);
            g_xc[i * (NH * NHID) + h * NHID + lane + 32] = elu1(vb);
        }
    }
}

// ============================================================
// gemm2: h2 = xc @ Wo + layer-2 score dots
// ============================================================
__global__ void gemm2_kernel(const float* __restrict__ Wo, const float* __restrict__ ao) {
    __shared__ __align__(16) float sxcT[32][68];
    __shared__ __align__(16) float sWo[32][20];
    __shared__ __align__(16) float sh2s[64][17];
    const int r0 = blockIdx.x * 64;
    const int tid = threadIdx.x;
    const int c4 = tid & 3, r = tid >> 2;
    float acc[4] = {};

    for (int k0 = 0; k0 < NFEAT; k0 += 32) {
        __syncthreads();
        #pragma unroll
        for (int i = tid; i < 2048; i += 256) {
            int k = i & 31, rr = i >> 5;
            sxcT[k][rr] = g_xc[(r0 + rr) * NFEAT + k0 + k];
        }
        #pragma unroll
        for (int i = tid; i < 512; i += 256) {
            int k = i >> 4, c = i & 15;
            sWo[k][c] = Wo[(k0 + k) * NCLS + c];
        }
        __syncthreads();
        #pragma unroll
        for (int k = 0; k < 32; k++) {
            float a = sxcT[k][r];
            float4 b = *(const float4*)&sWo[k][c4 * 4];
            acc[0] += a * b.x; acc[1] += a * b.y; acc[2] += a * b.z; acc[3] += a * b.w;
        }
    }
    *(float4*)&g_h2[(r0 + r) * NCLS + c4 * 4] = make_float4(acc[0], acc[1], acc[2], acc[3]);
    sh2s[r][c4 * 4 + 0] = acc[0];
    sh2s[r][c4 * 4 + 1] = acc[1];
    sh2s[r][c4 * 4 + 2] = acc[2];
    sh2s[r][c4 * 4 + 3] = acc[3];
    __syncthreads();
    if (tid < 64) {
        float ss = 0.f, sd = 0.f;
        #pragma unroll
        for (int c = 0; c < NCLS; c++) {
            float hv = sh2s[tid][c];
            ss += hv * ao[c];
            sd += hv * ao[NCLS + c];
        }
        g_s2src[r0 + tid] = ss;
        g_s2dst[r0 + tid] = sd;
    }
}

// ============================================================
// scan2: per-column scans for layer 2
// ============================================================
__device__ __forceinline__ void chunk_offsets(const float* totA, const float* totB,
                                              float* offA, float* offB, int tid) {
    if (tid < 32) {
        float pb[8], pa[8];
        float sb = 0.f, sa = 0.f;
        #pragma unroll
        for (int j = 0; j < 8; j++) { sb += totB[tid * 8 + j]; pb[j] = sb; }
        #pragma unroll
        for (int j = 7; j >= 0; j--) { sa += totA[tid * 8 + j]; pa[j] = sa; }
        float eb = sb;
        #pragma unroll
        for (int o = 1; o < 32; o <<= 1) {
            float t = __shfl_up_sync(0xffffffffu, eb, o);
            if (tid >= o) eb += t;
        }
        eb -= sb;
        float ea = sa;
        #pragma unroll
        for (int o = 1; o < 32; o <<= 1) {
            float t = __shfl_down_sync(0xffffffffu, ea, o);
            if (tid + o < 32) ea += t;
        }
        ea -= sa;
        #pragma unroll
        for (int j = 0; j < 8; j++) {
            offB[tid * 8 + j + 1] = eb + pb[j];
            offA[tid * 8 + j]     = ea + pa[j];
        }
        if (tid == 0)  offB[0]   = 0.f;
        if (tid == 31) offA[256] = 0.f;
    }
}

__global__ void scan2_kernel() {
    const int c = blockIdx.x;
    const int tid = threadIdx.x;
    __shared__ float totA[256], totB[256];
    __shared__ float offA[257], offB[257];
    float a_loc[16], b_loc[16];
    const int base = tid * 16;
    #pragma unroll
    for (int q = 0; q < 16; q++) {
        int k = base + q;
        float hv = g_h2[g_pm2[k] * NCLS + c];
        a_loc[q] = g_e2a[k] * hv;
        b_loc[q] = g_e2b[k] * hv;
    }
    #pragma unroll
    for (int q = 1; q < 16; q++) b_loc[q] += b_loc[q - 1];
    #pragma unroll
    for (int q = 14; q >= 0; q--) a_loc[q] += a_loc[q + 1];
    totB[tid] = b_loc[15]; totA[tid] = a_loc[0];
    __syncthreads();
    chunk_offsets(totA, totB, offA, offB, tid);
    __syncthreads();
    const float ob = offB[tid];
    const float oa = offA[tid + 1];
    float* E = g_E2 + c;
    float* F = g_F2 + c;
    #pragma unroll
    for (int q = 0; q < 16; q++) {
        E[(base + q) * NCLS]     = a_loc[q] + oa;
        F[(base + q + 1) * NCLS] = b_loc[q] + ob;
    }
    if (tid == 0)   F[0] = 0.f;
    if (tid == 255) E[NN * NCLS] = 0.f;
}

// ============================================================
// row2: 128 rows per block (512 threads) + combine + log_softmax
// ============================================================
__global__ __launch_bounds__(512) void row2_kernel(float* __restrict__ out) {
    __shared__ float st[4096];
    const int warp = threadIdx.x >> 5, lane = threadIdx.x & 31;
    for (int q = threadIdx.x; q < 4096; q += 512) st[q] = g_ts2[q];
    __syncthreads();
    const int rbase = blockIdx.x * 128 + warp * 8;
    const float s_l = g_s2src[rbase + (lane & 7)];
    const float w1_l = __expf(s_l), w2_l = __expf(ALPHA * s_l);
    int lo = 0, hi = 4096; const float thr = -s_l;
    while (lo < hi) { int mid = (lo + hi) >> 1; if (st[mid] <= thr) lo = mid + 1; else hi = mid; }

    #pragma unroll
    for (int rr = 0; rr < 8; rr++) {
        const int i = rbase + rr;
        const int r  = __shfl_sync(0xffffffffu, lo, rr);
        const float w1 = __shfl_sync(0xffffffffu, w1_l, rr);
        const float w2 = __shfl_sync(0xffffffffu, w2_l, rr);
        const float den = w1 * g_es2[r] + w2 * g_fs2[r];
        const float invden = 1.f / den;
        float v = -1e30f;
        if (lane < NCLS)
            v = elu1((w1 * g_E2[r * NCLS + lane] + w2 * g_F2[r * NCLS + lane]) * invden);
        float m = v;
        #pragma unroll
        for (int o = 8; o; o >>= 1) m = fmaxf(m, __shfl_xor_sync(0xffffffffu, m, o));
        float s = __expf(v - m);
        #pragma unroll
        for (int o = 8; o; o >>= 1) s += __shfl_xor_sync(0xffffffffu, s, o);
        const float lse = m + __logf(s);
        if (lane < NCLS) out[i * NCLS + lane] = v - lse;
    }
}

// ============================================================
extern "C" void kernel_launch(void* const* d_in, const int* in_sizes, int n_in,
                              void* d_out, int out_size) {
    const float* x  = (const float*)d_in[0];
    const float* Wh = (const float*)d_in[1];
    const float* ah = (const float*)d_in[2];
    const float* Wo = (const float*)d_in[3];
    const float* ao = (const float*)d_in[4];
    float* out = (float*)d_out;

    gemm1_kernel<<<dim3(NN / 128, 4), 256>>>(x, Wh, ah);
    sort1_kernel<<<NH, 1024>>>();
    scan1_kernel<<<dim3(NT, NH), 256>>>();
    row1_kernel<<<dim3(NN / 128, NH), 512>>>();
    gemm2_kernel<<<NN / 64, 256>>>(Wo, ao);
    sort2_kernel<<<1, 1024>>>();
    scan2_kernel<<<NCLS, 256>>>();
    row2_kernel<<<NN / 128, 512>>>(out);
}